// round 2
// baseline (speedup 1.0000x reference)
#include <cuda_runtime.h>
#include <stdint.h>
#include <math.h>

#define NN   8192
#define WPR  256          // 8192 bits / 32 per word

// ---------------- device scratch (static, no allocation) ----------------
static __device__ uint32_t g_adj0[NN * WPR];   // original adjacency bitmask (8 MB)
static __device__ uint32_t g_adjL[NN * WPR];   // per-layer resampled adjacency (8 MB)
static __device__ float    g_dinv[NN];
static __device__ float    g_za[NN * 64];
static __device__ float    g_zb[NN * 64];
static __device__ float    g_gt[NN * 64];
static __device__ int      g_is64;

// ---------------- Threefry-2x32 (exact JAX constants/rounds) ----------------
__host__ __device__ __forceinline__ void tf2x32(uint32_t k0, uint32_t k1,
                                                uint32_t &x0, uint32_t &x1) {
  uint32_t k2 = k0 ^ k1 ^ 0x1BD11BDAu;
  x0 += k0; x1 += k1;
#define TF_RND(r) { x0 += x1; x1 = (x1 << (r)) | (x1 >> (32 - (r))); x1 ^= x0; }
  TF_RND(13) TF_RND(15) TF_RND(26) TF_RND(6)
  x0 += k1; x1 += k2 + 1u;
  TF_RND(17) TF_RND(29) TF_RND(16) TF_RND(24)
  x0 += k2; x1 += k0 + 2u;
  TF_RND(13) TF_RND(15) TF_RND(26) TF_RND(6)
  x0 += k0; x1 += k1 + 3u;
  TF_RND(17) TF_RND(29) TF_RND(16) TF_RND(24)
  x0 += k1; x1 += k2 + 4u;
  TF_RND(13) TF_RND(15) TF_RND(26) TF_RND(6)
  x0 += k2; x1 += k0 + 5u;
#undef TF_RND
}

// jax_threefry_partitionable=True 32-bit random_bits:
// element n -> counter (n>>32, n&0xffffffff) = (0, n) here; bits = out0 ^ out1
__device__ __forceinline__ float jax_uniform01(uint32_t k0, uint32_t k1, uint32_t n) {
  uint32_t x0 = 0u, x1 = n;
  tf2x32(k0, k1, x0, x1);
  uint32_t bits = x0 ^ x1;
  return __uint_as_float((bits >> 9) | 0x3f800000u) - 1.0f;
}

// ---------------- kernels ----------------
__global__ void k_clear(uint32_t *p) {
  p[blockIdx.x * blockDim.x + threadIdx.x] = 0u;
}

// decide whether edge_index arrived as int64 or int32 (x64-off JAX downcasts)
__global__ void k_detect(const void *ev) {
  if (threadIdx.x == 0 && blockIdx.x == 0) {
    const unsigned long long *p = (const unsigned long long *)ev;
    int is64 = 1;
    for (int k = 0; k < 512; k++)
      if (p[k] > 8191ull) { is64 = 0; break; }
    g_is64 = is64;
  }
}

__global__ void k_scatter(uint32_t *adj0, const void *ev, int n) {
  int k = blockIdx.x * blockDim.x + threadIdx.x;
  if (k >= n) return;
  int r, c;
  if (g_is64) {
    const long long *e = (const long long *)ev;
    r = (int)e[k]; c = (int)e[k + n];
  } else {
    const int *e = (const int *)ev;
    r = e[k]; c = e[k + n];
  }
  atomicOr(&adj0[r * WPR + (c >> 5)], 1u << (c & 31));
}

__global__ void k_dinv(const uint32_t *__restrict__ adj, float *__restrict__ dinv) {
  int i = blockIdx.x * blockDim.x + threadIdx.x;
  if (i >= NN) return;
  const uint32_t *row = adj + i * WPR;
  int s = 1;  // self loop
#pragma unroll 8
  for (int w = 0; w < WPR; w++) s += __popc(row[w]);
  dinv[i] = 1.0f / sqrtf((float)s);
}

// g = dinv_row * (zin @ W)
template <int KIN, int C>
__global__ void k_gemm(const float *__restrict__ zin, const float *__restrict__ W,
                       const float *__restrict__ dinv, float *__restrict__ gt) {
  __shared__ float Ws[KIN * C];
  int tid = threadIdx.y * C + threadIdx.x;
  for (int t = tid; t < KIN * C; t += blockDim.y * C) Ws[t] = W[t];
  __syncthreads();
  int row = blockIdx.x * blockDim.y + threadIdx.y;
  const float *zr = zin + row * KIN;
  float acc = 0.f;
#pragma unroll
  for (int k = 0; k < KIN; k++) acc += zr[k] * Ws[k * C + threadIdx.x];
  gt[row * C + threadIdx.x] = dinv[row] * acc;
}

// z_i = dropout(relu(dinv_i * (g_i + sum_{j in adj row i} g_j) + b))
template <int C>
__global__ void k_aggregate(const uint32_t *__restrict__ adj, const float *__restrict__ gt,
                            const float *__restrict__ dinv, const float *__restrict__ b,
                            float *__restrict__ zout, uint32_t kd0, uint32_t kd1) {
  int i = blockIdx.x;
  int c = threadIdx.x;                 // blockDim.x == C
  __shared__ uint32_t words[WPR];
  for (int w = c; w < WPR; w += C) words[w] = adj[i * WPR + w];
  __syncthreads();
  float acc = gt[i * C + c];           // identity self-loop term (g_i = dinv_i*h_i)
  for (int w = 0; w < WPR; w++) {
    uint32_t m = words[w];             // uniform across the block -> no divergence
    while (m) {
      int bit = __ffs(m) - 1; m &= m - 1;
      int j = (w << 5) + bit;
      acc += gt[j * C + c];
    }
  }
  float v = dinv[i] * acc + b[c];
  v = fmaxf(v, 0.0f);
  uint32_t n = (uint32_t)(i * C + c);
  float u = jax_uniform01(kd0, kd1, n);
  zout[i * C + c] = (u < 0.9f) ? (v / 0.9f) : 0.0f;
}

// adjL = adj0 * (uniform(kb, [N,N]) < sigmoid(z @ z.T)), evaluated only on adj0 bits
__global__ void k_resample(const uint32_t *__restrict__ adj0, uint32_t *__restrict__ adjL,
                           const float *__restrict__ z, uint32_t kb0, uint32_t kb1) {
  int i = blockIdx.x;
  int t = threadIdx.x;                 // 64 threads, each owns 4 words
  __shared__ float zi[64];
  zi[t] = z[i * 64 + t];
  __syncthreads();
#pragma unroll
  for (int ww = 0; ww < 4; ww++) {
    int w = t * 4 + ww;
    uint32_t m = adj0[i * WPR + w];
    uint32_t out = 0u;
    while (m) {
      int bit = __ffs(m) - 1; m &= m - 1;
      int j = (w << 5) + bit;
      const float *zj = z + j * 64;
      float d = 0.f;
#pragma unroll
      for (int c2 = 0; c2 < 64; c2++) d += zi[c2] * zj[c2];
      float p = 1.0f / (1.0f + expf(-d));
      uint32_t n = (uint32_t)i * (uint32_t)NN + (uint32_t)j;
      float u = jax_uniform01(kb0, kb1, n);
      if (u < p) out |= (1u << bit);
    }
    adjL[i * WPR + w] = out;
  }
}

// ---------------- launch ----------------
extern "C" void kernel_launch(void *const *d_in, const int *in_sizes, int n_in,
                              void *d_out, int out_size) {
  const float *x  = (const float *)d_in[0];
  const float *W0 = (const float *)d_in[1];
  const float *b0 = (const float *)d_in[2];
  const float *W1 = (const float *)d_in[3];
  const float *b1 = (const float *)d_in[4];
  const float *W2 = (const float *)d_in[5];
  const float *b2 = (const float *)d_in[6];
  const void  *ei = (const void  *)d_in[7];
  int nE = in_sizes[7] / 2;

  // JAX key schedule on host (pure constants), partitionable threefry:
  // r_i = fold_in(key(42), i) = block((0,42),(0,i))
  // split(r_i): kd = block(r_i,(0,0)), kb = block(r_i,(0,1))   [fold-like split]
  uint32_t kd[3][2], kb[3][2];
  for (int i = 0; i < 3; i++) {
    uint32_t f0 = 0u, f1 = (uint32_t)i;
    tf2x32(0u, 42u, f0, f1);                       // r_i
    uint32_t a0 = 0u, a1 = 0u; tf2x32(f0, f1, a0, a1);  // block(r_i,(0,0))
    uint32_t c0 = 0u, c1 = 1u; tf2x32(f0, f1, c0, c1);  // block(r_i,(0,1))
    kd[i][0] = a0; kd[i][1] = a1;
    kb[i][0] = c0; kb[i][1] = c1;
  }

  uint32_t *adj0, *adjL; float *dinv, *za, *zb, *gt;
  cudaGetSymbolAddress((void **)&adj0, g_adj0);
  cudaGetSymbolAddress((void **)&adjL, g_adjL);
  cudaGetSymbolAddress((void **)&dinv, g_dinv);
  cudaGetSymbolAddress((void **)&za,   g_za);
  cudaGetSymbolAddress((void **)&zb,   g_zb);
  cudaGetSymbolAddress((void **)&gt,   g_gt);

  k_clear<<<(NN * WPR) / 1024, 1024>>>(adj0);
  k_detect<<<1, 32>>>(ei);
  k_scatter<<<(nE + 255) / 256, 256>>>(adj0, ei, nE);

  // ---- layer 0 (adj = adj0) ----
  k_dinv<<<NN / 256, 256>>>(adj0, dinv);
  { dim3 bd(64, 4); k_gemm<128, 64><<<NN / 4, bd>>>(x, W0, dinv, gt); }
  k_aggregate<64><<<NN, 64>>>(adj0, gt, dinv, b0, za, kd[0][0], kd[0][1]);
  k_resample<<<NN, 64>>>(adj0, adjL, za, kb[0][0], kb[0][1]);

  // ---- layer 1 (adj = adj0 * sample0) ----
  k_dinv<<<NN / 256, 256>>>(adjL, dinv);
  { dim3 bd(64, 4); k_gemm<64, 64><<<NN / 4, bd>>>(za, W1, dinv, gt); }
  k_aggregate<64><<<NN, 64>>>(adjL, gt, dinv, b1, zb, kd[1][0], kd[1][1]);
  k_resample<<<NN, 64>>>(adj0, adjL, zb, kb[1][0], kb[1][1]);

  // ---- layer 2 (adj = adj0 * sample1), output straight to d_out ----
  k_dinv<<<NN / 256, 256>>>(adjL, dinv);
  { dim3 bd(32, 8); k_gemm<64, 32><<<NN / 8, bd>>>(zb, W2, dinv, gt); }
  k_aggregate<32><<<NN, 32>>>(adjL, gt, dinv, b2, (float *)d_out, kd[2][0], kd[2][1]);
}

// round 3
// speedup vs baseline: 2.0253x; 2.0253x over previous
#include <cuda_runtime.h>
#include <stdint.h>
#include <math.h>

#define NN   8192
#define WPR  256          // 8192 bits / 32 per word
#define EDGE_CAP 1024     // max row degree (mean 32, max ~60 for this graph)

// ---------------- device scratch (static, no allocation) ----------------
static __device__ uint32_t g_adj0[NN * WPR];   // original adjacency bitmask (8 MB)
static __device__ uint32_t g_adjL[NN * WPR];   // per-layer resampled adjacency (8 MB)
static __device__ float    g_dinv[NN];
static __device__ float    g_za[NN * 64];
static __device__ float    g_zb[NN * 64];
static __device__ float    g_gt[NN * 64];
static __device__ int      g_is64;

// ---------------- Threefry-2x32 (exact JAX constants/rounds) ----------------
__host__ __device__ __forceinline__ void tf2x32(uint32_t k0, uint32_t k1,
                                                uint32_t &x0, uint32_t &x1) {
  uint32_t k2 = k0 ^ k1 ^ 0x1BD11BDAu;
  x0 += k0; x1 += k1;
#define TF_RND(r) { x0 += x1; x1 = (x1 << (r)) | (x1 >> (32 - (r))); x1 ^= x0; }
  TF_RND(13) TF_RND(15) TF_RND(26) TF_RND(6)
  x0 += k1; x1 += k2 + 1u;
  TF_RND(17) TF_RND(29) TF_RND(16) TF_RND(24)
  x0 += k2; x1 += k0 + 2u;
  TF_RND(13) TF_RND(15) TF_RND(26) TF_RND(6)
  x0 += k0; x1 += k1 + 3u;
  TF_RND(17) TF_RND(29) TF_RND(16) TF_RND(24)
  x0 += k1; x1 += k2 + 4u;
  TF_RND(13) TF_RND(15) TF_RND(26) TF_RND(6)
  x0 += k2; x1 += k0 + 5u;
#undef TF_RND
}

// jax_threefry_partitionable=True 32-bit random_bits:
// element n -> counter (0, n); bits = out0 ^ out1
__device__ __forceinline__ float jax_uniform01(uint32_t k0, uint32_t k1, uint32_t n) {
  uint32_t x0 = 0u, x1 = n;
  tf2x32(k0, k1, x0, x1);
  uint32_t bits = x0 ^ x1;
  return __uint_as_float((bits >> 9) | 0x3f800000u) - 1.0f;
}

// ---------------- kernels ----------------
__global__ void k_clear(uint32_t *p) {
  p[blockIdx.x * blockDim.x + threadIdx.x] = 0u;
}

// one warp, ballot: is edge_index int64 (all hi-words < 8192) or int32?
__global__ void k_detect(const void *ev) {
  const unsigned long long *p = (const unsigned long long *)ev;
  int lane = threadIdx.x;
  bool big = false;
  for (int k = lane; k < 512; k += 32) big |= (p[k] > 8191ull);
  unsigned m = __ballot_sync(0xffffffffu, big);
  if (lane == 0) g_is64 = (m == 0u);
}

__global__ void k_scatter(uint32_t *adj0, const void *ev, int n) {
  int k = blockIdx.x * blockDim.x + threadIdx.x;
  if (k >= n) return;
  int r, c;
  if (g_is64) {
    const long long *e = (const long long *)ev;
    r = (int)e[k]; c = (int)e[k + n];
  } else {
    const int *e = (const int *)ev;
    r = e[k]; c = e[k + n];
  }
  atomicOr(&adj0[r * WPR + (c >> 5)], 1u << (c & 31));
}

// one warp per row, uint4 loads
__global__ void k_dinv_fast(const uint32_t *__restrict__ adj, float *__restrict__ dinv) {
  int row = (blockIdx.x * blockDim.x + threadIdx.x) >> 5;
  int lane = threadIdx.x & 31;
  const uint4 *r = (const uint4 *)(adj + row * WPR);
  int s = 0;
#pragma unroll
  for (int kk = 0; kk < 2; kk++) {
    uint4 v = r[lane + kk * 32];
    s += __popc(v.x) + __popc(v.y) + __popc(v.z) + __popc(v.w);
  }
#pragma unroll
  for (int d = 16; d; d >>= 1) s += __shfl_down_sync(0xffffffffu, s, d);
  if (lane == 0) dinv[row] = rsqrtf((float)(s + 1));
}

// g = dinv_row * (zin @ W)
template <int KIN, int C>
__global__ void k_gemm(const float *__restrict__ zin, const float *__restrict__ W,
                       const float *__restrict__ dinv, float *__restrict__ gt) {
  __shared__ float Ws[KIN * C];
  int tid = threadIdx.y * C + threadIdx.x;
  for (int t = tid; t < KIN * C; t += blockDim.y * C) Ws[t] = W[t];
  __syncthreads();
  int row = blockIdx.x * blockDim.y + threadIdx.y;
  const float *zr = zin + row * KIN;
  float acc = 0.f;
#pragma unroll
  for (int k = 0; k < KIN; k++) acc += zr[k] * Ws[k * C + threadIdx.x];
  gt[row * C + threadIdx.x] = dinv[row] * acc;
}

// z_i = dropout(relu(dinv_i * (g_i + sum_{j in row i} g_j) + b))
// Deterministic edge-list build (prefix scan), then tight gather loop.
template <int C>
__global__ void k_aggregate(const uint32_t *__restrict__ adj, const float *__restrict__ gt,
                            const float *__restrict__ dinv, const float *__restrict__ b,
                            float *__restrict__ zout, uint32_t kd0, uint32_t kd1) {
  const int WPT = WPR / C;             // words per thread
  int i = blockIdx.x;
  int t = threadIdx.x;                 // blockDim.x == C (64 or 32)
  __shared__ int edges[EDGE_CAP];
  __shared__ int wsum[2];
  __shared__ int tot;

  uint32_t mw[WPT];
  int myc = 0;
#pragma unroll
  for (int kk = 0; kk < WPT; kk++) {
    mw[kk] = adj[i * WPR + t + kk * C];
    myc += __popc(mw[kk]);
  }
  // exclusive prefix over C threads (1 or 2 warps)
  int lane = t & 31, wid = t >> 5;
  int v = myc;
#pragma unroll
  for (int d = 1; d < 32; d <<= 1) {
    int n = __shfl_up_sync(0xffffffffu, v, d);
    if (lane >= d) v += n;
  }
  if (lane == 31) wsum[wid] = v;
  __syncthreads();
  int off = v - myc + ((C > 32 && wid == 1) ? wsum[0] : 0);
  if (t == C - 1) tot = off + myc;
#pragma unroll
  for (int kk = 0; kk < WPT; kk++) {
    uint32_t m = mw[kk];
    while (m) {
      int bit = __ffs(m) - 1; m &= m - 1;
      edges[off++] = ((t + kk * C) << 5) + bit;
    }
  }
  __syncthreads();

  int ne = tot;
  float acc = gt[i * C + t];           // identity self-loop term
  for (int e = 0; e < ne; e++) acc += gt[edges[e] * C + t];

  float val = dinv[i] * acc + b[t];
  val = fmaxf(val, 0.0f);
  float u = jax_uniform01(kd0, kd1, (uint32_t)(i * C + t));
  zout[i * C + t] = (u < 0.9f) ? (val / 0.9f) : 0.0f;
}

// adjL = adj0 * (uniform < sigmoid(z z^T)) on original edges; also emits dinv of adjL.
__global__ void k_resample(const uint32_t *__restrict__ adj0, uint32_t *__restrict__ adjL,
                           const float *__restrict__ z, float *__restrict__ dinv,
                           uint32_t kb0, uint32_t kb1) {
  int i = blockIdx.x;
  int t = threadIdx.x;                 // 64
  __shared__ float zi[64];
  __shared__ uint32_t outw[WPR];
  __shared__ int edges[EDGE_CAP];
  __shared__ int cnt;
  __shared__ int part[2];

  zi[t] = z[i * 64 + t];
  if (t == 0) cnt = 0;
#pragma unroll
  for (int kk = 0; kk < 4; kk++) outw[t + kk * 64] = 0u;
  __syncthreads();

#pragma unroll
  for (int kk = 0; kk < 4; kk++) {
    uint32_t m = adj0[i * WPR + t + kk * 64];
    while (m) {
      int bit = __ffs(m) - 1; m &= m - 1;
      int e = atomicAdd(&cnt, 1);      // order-independent work: ok
      edges[e] = ((t + kk * 64) << 5) + bit;
    }
  }
  __syncthreads();

  int ne = cnt;
  for (int e = t; e < ne; e += 64) {
    int j = edges[e];
    const float4 *zj = (const float4 *)(z + j * 64);
    const float4 *zi4 = (const float4 *)zi;
    float d = 0.f;
#pragma unroll
    for (int c = 0; c < 16; c++) {
      float4 a = zi4[c], bb = zj[c];
      d += a.x * bb.x + a.y * bb.y + a.z * bb.z + a.w * bb.w;
    }
    float p = 1.0f / (1.0f + expf(-d));
    float u = jax_uniform01(kb0, kb1, (uint32_t)i * (uint32_t)NN + (uint32_t)j);
    if (u < p) atomicOr(&outw[j >> 5], 1u << (j & 31));
  }
  __syncthreads();

  int s = 0;
#pragma unroll
  for (int kk = 0; kk < 4; kk++) {
    uint32_t v = outw[t + kk * 64];
    adjL[i * WPR + t + kk * 64] = v;
    s += __popc(v);
  }
#pragma unroll
  for (int d = 16; d; d >>= 1) s += __shfl_down_sync(0xffffffffu, s, d);
  if ((t & 31) == 0) part[t >> 5] = s;
  __syncthreads();
  if (t == 0) dinv[i] = rsqrtf((float)(part[0] + part[1] + 1));
}

// ---------------- launch ----------------
extern "C" void kernel_launch(void *const *d_in, const int *in_sizes, int n_in,
                              void *d_out, int out_size) {
  const float *x  = (const float *)d_in[0];
  const float *W0 = (const float *)d_in[1];
  const float *b0 = (const float *)d_in[2];
  const float *W1 = (const float *)d_in[3];
  const float *b1 = (const float *)d_in[4];
  const float *W2 = (const float *)d_in[5];
  const float *b2 = (const float *)d_in[6];
  const void  *ei = (const void  *)d_in[7];
  int nE = in_sizes[7] / 2;

  // JAX key schedule (partitionable threefry), host-side constants:
  // r_i = fold_in(key(42), i) = block((0,42),(0,i))
  // split: kd = block(r_i,(0,0)), kb = block(r_i,(0,1))
  uint32_t kd[3][2], kb[3][2];
  for (int i = 0; i < 3; i++) {
    uint32_t f0 = 0u, f1 = (uint32_t)i;
    tf2x32(0u, 42u, f0, f1);
    uint32_t a0 = 0u, a1 = 0u; tf2x32(f0, f1, a0, a1);
    uint32_t c0 = 0u, c1 = 1u; tf2x32(f0, f1, c0, c1);
    kd[i][0] = a0; kd[i][1] = a1;
    kb[i][0] = c0; kb[i][1] = c1;
  }

  uint32_t *adj0, *adjL; float *dinv, *za, *zb, *gt;
  cudaGetSymbolAddress((void **)&adj0, g_adj0);
  cudaGetSymbolAddress((void **)&adjL, g_adjL);
  cudaGetSymbolAddress((void **)&dinv, g_dinv);
  cudaGetSymbolAddress((void **)&za,   g_za);
  cudaGetSymbolAddress((void **)&zb,   g_zb);
  cudaGetSymbolAddress((void **)&gt,   g_gt);

  k_clear<<<(NN * WPR) / 1024, 1024>>>(adj0);
  k_detect<<<1, 32>>>(ei);
  k_scatter<<<(nE + 255) / 256, 256>>>(adj0, ei, nE);

  // ---- layer 0 (adj = adj0) ----
  k_dinv_fast<<<NN / 8, 256>>>(adj0, dinv);
  { dim3 bd(64, 4); k_gemm<128, 64><<<NN / 4, bd>>>(x, W0, dinv, gt); }
  k_aggregate<64><<<NN, 64>>>(adj0, gt, dinv, b0, za, kd[0][0], kd[0][1]);
  k_resample<<<NN, 64>>>(adj0, adjL, za, dinv, kb[0][0], kb[0][1]);   // also writes dinv(adjL)

  // ---- layer 1 ----
  { dim3 bd(64, 4); k_gemm<64, 64><<<NN / 4, bd>>>(za, W1, dinv, gt); }
  k_aggregate<64><<<NN, 64>>>(adjL, gt, dinv, b1, zb, kd[1][0], kd[1][1]);
  k_resample<<<NN, 64>>>(adj0, adjL, zb, dinv, kb[1][0], kb[1][1]);   // also writes dinv(adjL)

  // ---- layer 2 (output straight to d_out) ----
  { dim3 bd(32, 8); k_gemm<64, 32><<<NN / 8, bd>>>(zb, W2, dinv, gt); }
  k_aggregate<32><<<NN, 32>>>(adjL, gt, dinv, b2, (float *)d_out, kd[2][0], kd[2][1]);
}

// round 7
// speedup vs baseline: 4.1358x; 2.0421x over previous
#include <cuda_runtime.h>
#include <stdint.h>
#include <math.h>

#define NN   8192
#define WPR  256          // 8192 bits / 32 per word
#define EDGE_CAP 1024

// ---------------- device scratch (static, no allocation) ----------------
static __device__ uint32_t g_adj0[NN * WPR];
static __device__ uint32_t g_adjL[NN * WPR];
static __device__ float    g_dinv[NN];
static __device__ float    g_za[NN * 64];
static __device__ float    g_zb[NN * 64];
static __device__ float    g_gt[NN * 64];
static __device__ int      g_is64;

// ---------------- Threefry-2x32 (exact JAX constants/rounds) ----------------
__host__ __device__ __forceinline__ void tf2x32(uint32_t k0, uint32_t k1,
                                                uint32_t &x0, uint32_t &x1) {
  uint32_t k2 = k0 ^ k1 ^ 0x1BD11BDAu;
  x0 += k0; x1 += k1;
#define TF_RND(r) { x0 += x1; x1 = (x1 << (r)) | (x1 >> (32 - (r))); x1 ^= x0; }
  TF_RND(13) TF_RND(15) TF_RND(26) TF_RND(6)
  x0 += k1; x1 += k2 + 1u;
  TF_RND(17) TF_RND(29) TF_RND(16) TF_RND(24)
  x0 += k2; x1 += k0 + 2u;
  TF_RND(13) TF_RND(15) TF_RND(26) TF_RND(6)
  x0 += k0; x1 += k1 + 3u;
  TF_RND(17) TF_RND(29) TF_RND(16) TF_RND(24)
  x0 += k1; x1 += k2 + 4u;
  TF_RND(13) TF_RND(15) TF_RND(26) TF_RND(6)
  x0 += k2; x1 += k0 + 5u;
#undef TF_RND
}

// partitionable threefry: element n -> counter (0, n); bits = out0 ^ out1
__device__ __forceinline__ float jax_uniform01(uint32_t k0, uint32_t k1, uint32_t n) {
  uint32_t x0 = 0u, x1 = n;
  tf2x32(k0, k1, x0, x1);
  uint32_t bits = x0 ^ x1;
  return __uint_as_float((bits >> 9) | 0x3f800000u) - 1.0f;
}

// ---------------- kernels ----------------
__global__ void k_clear(uint32_t *p) {
  p[blockIdx.x * blockDim.x + threadIdx.x] = 0u;
}

__global__ void k_detect(const void *ev) {
  const unsigned long long *p = (const unsigned long long *)ev;
  int lane = threadIdx.x;
  bool big = false;
  for (int k = lane; k < 512; k += 32) big |= (p[k] > 8191ull);
  unsigned m = __ballot_sync(0xffffffffu, big);
  if (lane == 0) g_is64 = (m == 0u);
}

__global__ void k_scatter(uint32_t *adj0, const void *ev, int n) {
  int k = blockIdx.x * blockDim.x + threadIdx.x;
  if (k >= n) return;
  int r, c;
  if (g_is64) {
    const long long *e = (const long long *)ev;
    r = (int)e[k]; c = (int)e[k + n];
  } else {
    const int *e = (const int *)ev;
    r = e[k]; c = e[k + n];
  }
  atomicOr(&adj0[r * WPR + (c >> 5)], 1u << (c & 31));
}

// one warp per row, uint4 loads
__global__ void k_dinv_fast(const uint32_t *__restrict__ adj, float *__restrict__ dinv) {
  int row = (blockIdx.x * blockDim.x + threadIdx.x) >> 5;
  int lane = threadIdx.x & 31;
  const uint4 *r = (const uint4 *)(adj + row * WPR);
  int s = 0;
#pragma unroll
  for (int kk = 0; kk < 2; kk++) {
    uint4 v = r[lane + kk * 32];
    s += __popc(v.x) + __popc(v.y) + __popc(v.z) + __popc(v.w);
  }
#pragma unroll
  for (int d = 16; d; d >>= 1) s += __shfl_down_sync(0xffffffffu, s, d);
  if (lane == 0) dinv[row] = rsqrtf((float)(s + 1));
}

// g = dinv_row * (zin @ W)  — shared-tiled, register-blocked.
// 128 threads, 16 rows/block. Warp w -> rows 4w..4w+3. Lane -> cols lane(+32).
template <int KIN, int C>
__global__ void k_gemm_tiled(const float *__restrict__ zin, const float *__restrict__ W,
                             const float *__restrict__ dinv, float *__restrict__ gt) {
  const int NC = C / 32;               // cols per thread (1 or 2)
  __shared__ float Ws[KIN * C];
  __shared__ float Zs[16 * KIN];
  int t = threadIdx.x;
  int row0 = blockIdx.x * 16;
  for (int i = t; i < KIN * C / 4; i += 128)
    ((float4 *)Ws)[i] = ((const float4 *)W)[i];
  for (int i = t; i < 16 * KIN / 4; i += 128)
    ((float4 *)Zs)[i] = ((const float4 *)(zin + row0 * KIN))[i];
  __syncthreads();

  int warp = t >> 5, lane = t & 31;
  float acc[4][NC];
#pragma unroll
  for (int r = 0; r < 4; r++)
#pragma unroll
    for (int c = 0; c < NC; c++) acc[r][c] = 0.f;

#pragma unroll 4
  for (int k = 0; k < KIN; k++) {
    float wv[NC];
#pragma unroll
    for (int c = 0; c < NC; c++) wv[c] = Ws[k * C + lane + c * 32];
#pragma unroll
    for (int r = 0; r < 4; r++) {
      float zv = Zs[(warp * 4 + r) * KIN + k];   // broadcast within warp
#pragma unroll
      for (int c = 0; c < NC; c++) acc[r][c] += zv * wv[c];
    }
  }
#pragma unroll
  for (int r = 0; r < 4; r++) {
    int row = row0 + warp * 4 + r;
    float dv = dinv[row];
#pragma unroll
    for (int c = 0; c < NC; c++) gt[row * C + lane + c * 32] = dv * acc[r][c];
  }
}

// z_i = dropout(relu(dinv_i * (g_i + sum_j g_j) + b)); deterministic edge list + MLP-4 gather
template <int C>
__global__ void k_aggregate(const uint32_t *__restrict__ adj, const float *__restrict__ gt,
                            const float *__restrict__ dinv, const float *__restrict__ b,
                            float *__restrict__ zout, uint32_t kd0, uint32_t kd1) {
  const int WPT = WPR / C;
  int i = blockIdx.x;
  int t = threadIdx.x;                 // blockDim.x == C
  __shared__ int edges[EDGE_CAP];
  __shared__ int wsum[2];
  __shared__ int tot;

  uint32_t mw[WPT];
  int myc = 0;
#pragma unroll
  for (int kk = 0; kk < WPT; kk++) {
    mw[kk] = adj[i * WPR + t + kk * C];
    myc += __popc(mw[kk]);
  }
  int lane = t & 31, wid = t >> 5;
  int v = myc;
#pragma unroll
  for (int d = 1; d < 32; d <<= 1) {
    int n = __shfl_up_sync(0xffffffffu, v, d);
    if (lane >= d) v += n;
  }
  if (lane == 31) wsum[wid] = v;
  __syncthreads();
  int off = v - myc + ((C > 32 && wid == 1) ? wsum[0] : 0);
  if (t == C - 1) tot = off + myc;
#pragma unroll
  for (int kk = 0; kk < WPT; kk++) {
    uint32_t m = mw[kk];
    while (m) {
      int bit = __ffs(m) - 1; m &= m - 1;
      edges[off++] = ((t + kk * C) << 5) + bit;
    }
  }
  __syncthreads();

  int ne = tot;
  float a0 = gt[i * C + t], a1 = 0.f, a2 = 0.f, a3 = 0.f;
  int e = 0;
  for (; e + 4 <= ne; e += 4) {
    a0 += gt[edges[e] * C + t];
    a1 += gt[edges[e + 1] * C + t];
    a2 += gt[edges[e + 2] * C + t];
    a3 += gt[edges[e + 3] * C + t];
  }
  for (; e < ne; e++) a0 += gt[edges[e] * C + t];
  float acc = (a0 + a1) + (a2 + a3);

  float val = dinv[i] * acc + b[t];
  val = fmaxf(val, 0.0f);
  float u = jax_uniform01(kd0, kd1, (uint32_t)(i * C + t));
  zout[i * C + t] = (u < 0.9f) ? (val / 0.9f) : 0.0f;
}

// adjL = adj0 * (uniform < sigmoid(z z^T)) on original edges; also emits dinv(adjL).
// 128 threads: 16 groups of 8 threads per edge; UNIFORM trip count so all lanes
// of every warp reach the __shfl_down_sync together.
__global__ void k_resample(const uint32_t *__restrict__ adj0, uint32_t *__restrict__ adjL,
                           const float *__restrict__ z, float *__restrict__ dinv,
                           uint32_t kb0, uint32_t kb1) {
  int i = blockIdx.x;
  int t = threadIdx.x;                 // 128
  __shared__ float zi[64];
  __shared__ uint32_t outw[WPR];
  __shared__ int edges[EDGE_CAP];
  __shared__ int cnt;
  __shared__ int part[4];

  if (t < 64) zi[t] = z[i * 64 + t];
  if (t == 0) cnt = 0;
#pragma unroll
  for (int kk = 0; kk < 2; kk++) outw[t + kk * 128] = 0u;
  __syncthreads();

#pragma unroll
  for (int kk = 0; kk < 2; kk++) {
    uint32_t m = adj0[i * WPR + t + kk * 128];
    while (m) {
      int bit = __ffs(m) - 1; m &= m - 1;
      int e = atomicAdd(&cnt, 1);      // order-independent work
      edges[e] = ((t + kk * 128) << 5) + bit;
    }
  }
  __syncthreads();

  int ne = cnt;
  int g = t >> 3, s = t & 7;           // 16 groups x 8 lanes
  const float4 *zi4 = (const float4 *)zi;
  int nIter = (ne + 15) >> 4;          // uniform across the whole block
  for (int it = 0; it < nIter; it++) {
    int e = it * 16 + g;
    bool active = (e < ne);
    int j = active ? edges[e] : 0;     // inactive lanes read row 0 (harmless)
    const float4 *zj = (const float4 *)(z + j * 64);
    float4 a0 = zi4[s],     b0 = zj[s];
    float4 a1 = zi4[s + 8], b1 = zj[s + 8];
    float d = a0.x * b0.x + a0.y * b0.y + a0.z * b0.z + a0.w * b0.w
            + a1.x * b1.x + a1.y * b1.y + a1.z * b1.z + a1.w * b1.w;
#pragma unroll
    for (int o = 4; o; o >>= 1) d += __shfl_down_sync(0xffffffffu, d, o, 8);
    if (active && s == 0) {
      float p = 1.0f / (1.0f + expf(-d));
      float u = jax_uniform01(kb0, kb1, (uint32_t)i * (uint32_t)NN + (uint32_t)j);
      if (u < p) atomicOr(&outw[j >> 5], 1u << (j & 31));
    }
  }
  __syncthreads();

  int sdeg = 0;
#pragma unroll
  for (int kk = 0; kk < 2; kk++) {
    uint32_t v = outw[t + kk * 128];
    adjL[i * WPR + t + kk * 128] = v;
    sdeg += __popc(v);
  }
#pragma unroll
  for (int d = 16; d; d >>= 1) sdeg += __shfl_down_sync(0xffffffffu, sdeg, d);
  if ((t & 31) == 0) part[t >> 5] = sdeg;
  __syncthreads();
  if (t == 0) dinv[i] = rsqrtf((float)(part[0] + part[1] + part[2] + part[3] + 1));
}

// ---------------- launch ----------------
extern "C" void kernel_launch(void *const *d_in, const int *in_sizes, int n_in,
                              void *d_out, int out_size) {
  const float *x  = (const float *)d_in[0];
  const float *W0 = (const float *)d_in[1];
  const float *b0 = (const float *)d_in[2];
  const float *W1 = (const float *)d_in[3];
  const float *b1 = (const float *)d_in[4];
  const float *W2 = (const float *)d_in[5];
  const float *b2 = (const float *)d_in[6];
  const void  *ei = (const void  *)d_in[7];
  int nE = in_sizes[7] / 2;

  // JAX key schedule (partitionable threefry):
  // r_i = block((0,42),(0,i)); kd = block(r_i,(0,0)); kb = block(r_i,(0,1))
  uint32_t kd[3][2], kb[3][2];
  for (int i = 0; i < 3; i++) {
    uint32_t f0 = 0u, f1 = (uint32_t)i;
    tf2x32(0u, 42u, f0, f1);
    uint32_t a0 = 0u, a1 = 0u; tf2x32(f0, f1, a0, a1);
    uint32_t c0 = 0u, c1 = 1u; tf2x32(f0, f1, c0, c1);
    kd[i][0] = a0; kd[i][1] = a1;
    kb[i][0] = c0; kb[i][1] = c1;
  }

  uint32_t *adj0, *adjL; float *dinv, *za, *zb, *gt;
  cudaGetSymbolAddress((void **)&adj0, g_adj0);
  cudaGetSymbolAddress((void **)&adjL, g_adjL);
  cudaGetSymbolAddress((void **)&dinv, g_dinv);
  cudaGetSymbolAddress((void **)&za,   g_za);
  cudaGetSymbolAddress((void **)&zb,   g_zb);
  cudaGetSymbolAddress((void **)&gt,   g_gt);

  k_clear<<<(NN * WPR) / 1024, 1024>>>(adj0);
  k_detect<<<1, 32>>>(ei);
  k_scatter<<<(nE + 255) / 256, 256>>>(adj0, ei, nE);

  // ---- layer 0 (adj = adj0) ----
  k_dinv_fast<<<NN / 8, 256>>>(adj0, dinv);
  k_gemm_tiled<128, 64><<<NN / 16, 128>>>(x, W0, dinv, gt);
  k_aggregate<64><<<NN, 64>>>(adj0, gt, dinv, b0, za, kd[0][0], kd[0][1]);
  k_resample<<<NN, 128>>>(adj0, adjL, za, dinv, kb[0][0], kb[0][1]);

  // ---- layer 1 ----
  k_gemm_tiled<64, 64><<<NN / 16, 128>>>(za, W1, dinv, gt);
  k_aggregate<64><<<NN, 64>>>(adjL, gt, dinv, b1, zb, kd[1][0], kd[1][1]);
  k_resample<<<NN, 128>>>(adj0, adjL, zb, dinv, kb[1][0], kb[1][1]);

  // ---- layer 2 (output straight to d_out) ----
  k_gemm_tiled<64, 32><<<NN / 16, 128>>>(zb, W2, dinv, gt);
  k_aggregate<32><<<NN, 32>>>(adjL, gt, dinv, b2, (float *)d_out, kd[2][0], kd[2][1]);
}